// round 16
// baseline (speedup 1.0000x reference)
#include <cuda_runtime.h>
#include <cstdint>

typedef unsigned int u32;

// ---------- MUFU.TANH ----------
__device__ __forceinline__ float tanh_a(float x) {
    float r; asm("tanh.approx.f32 %0, %1;" : "=f"(r) : "f"(x)); return r;
}
// fp32 pair -> f16x2 hi + f16x2 lo (residual). {a0 -> lo half, a1 -> hi half}
__device__ __forceinline__ void split2h(float a0, float a1, u32& ph, u32& pl) {
    u32 h;
    asm("cvt.rn.f16x2.f32 %0, %1, %2;" : "=r"(h) : "f"(a1), "f"(a0));
    float b0, b1;
    asm("{\n\t.reg .f16 x, y;\n\tmov.b32 {x, y}, %2;\n\t"
        "cvt.f32.f16 %0, x;\n\tcvt.f32.f16 %1, y;\n\t}"
        : "=f"(b0), "=f"(b1) : "r"(h));
    ph = h;
    asm("cvt.rn.f16x2.f32 %0, %1, %2;" : "=r"(pl) : "f"(a1 - b1), "f"(a0 - b0));
}
// fp32 pair -> f16x2 (B build; residual dropped by design)
__device__ __forceinline__ u32 pack2h(float a0, float a1) {
    u32 h;
    asm("cvt.rn.f16x2.f32 %0, %1, %2;" : "=r"(h) : "f"(a1), "f"(a0));
    return h;
}

// ---------- warp MMA: D(16x8) += A(16x16,f16,row) * B(16x8,f16,col) ----------
__device__ __forceinline__ void mma16816(float* d, const u32* a, const u32* b,
                                         const float* c) {
    asm("mma.sync.aligned.m16n8k16.row.col.f32.f16.f16.f32 "
        "{%0,%1,%2,%3}, {%4,%5,%6,%7}, {%8,%9}, {%10,%11,%12,%13};"
        : "=f"(d[0]), "=f"(d[1]), "=f"(d[2]), "=f"(d[3])
        : "r"(a[0]), "r"(a[1]), "r"(a[2]), "r"(a[3]),
          "r"(b[0]), "r"(b[1]),
          "f"(c[0]), "f"(c[1]), "f"(c[2]), "f"(c[3]));
}

// ---------- cp.async ----------
__device__ __forceinline__ void cp16(u32 dst, const float* src) {
    asm volatile("cp.async.cg.shared.global [%0], [%1], 16;" :: "r"(dst), "l"(src));
}
__device__ __forceinline__ void cp_commit() { asm volatile("cp.async.commit_group;"); }
__device__ __forceinline__ void cp_wait2()  { asm volatile("cp.async.wait_group 2;"); }
__device__ __forceinline__ void cp_wait0()  { asm volatile("cp.async.wait_group 0;"); }

#define WPB    4
#define STAGES 4
#define GROUP  16
// stage float layout: x[16][8] @0, h[16][16] @128, c[16][16] @384
#define ST_X 0
#define ST_H 128
#define ST_C 384
#define ST_F 640
#define ST_BYTES (ST_F * 4)

__device__ __forceinline__ void issue_group(u32 sb, int lane, int n0,
                                            const float* __restrict__ x,
                                            const float* __restrict__ h,
                                            const float* __restrict__ c)
{
    const int l4 = lane * 4;
    const int l16 = lane * 16;
    cp16(sb + ST_H * 4 + l16,         h + n0 * 16 + l4);
    cp16(sb + (ST_H + 128) * 4 + l16, h + n0 * 16 + 128 + l4);
    cp16(sb + ST_C * 4 + l16,         c + n0 * 16 + l4);
    cp16(sb + (ST_C + 128) * 4 + l16, c + n0 * 16 + 128 + l4);
    cp16(sb + ST_X * 4 + l16,         x + n0 * 8 + l4);
}

__global__ __launch_bounds__(128, 4)
void gconvlstm_mma(const float* __restrict__ x,
                   const float* __restrict__ h,
                   const float* __restrict__ c,
                   const float* __restrict__ Wx, const float* __restrict__ bx,
                   const float* __restrict__ Wh, const float* __restrict__ bh,
                   const float* __restrict__ wp, const float* __restrict__ bg,
                   const float* __restrict__ wl, const float* __restrict__ blin,
                   float* __restrict__ out,
                   float* __restrict__ h_new,
                   float* __restrict__ c_new,
                   int N)
{
    __shared__ __align__(16) float ring[WPB][STAGES][ST_F];   // 40960 B (wbuf overlaid)
    __shared__ __align__(16) float4 epi[16];                  // {0.5wp0,0.5wp1,0.5wp2,wld}
    __shared__ float sbl;

    const int tid  = threadIdx.x;
    const int lane = tid & 31;
    const int warp = tid >> 5;
    const int m    = lane & 3;     // threadID_in_group
    const int r0   = lane >> 2;    // groupID = fragment row

    // ---- stage weight matrix into smem (OVERLAID on ring; init-only lifetime) ----
    float* wbuf = &ring[0][0][0];                 // [32][64], rows 25-31 zero
    for (int i = tid; i < 32 * 64; i += 128) {
        int k = i >> 6, n = i & 63;
        float v = 0.0f;
        if (k < 8)        v = Wx[k * 64 + n];
        else if (k < 24)  v = Wh[(k - 8) * 64 + n];
        else if (k == 24) v = bx[n] + bh[n] + bg[n];
        if (n < 32 || n >= 48) v *= 0.5f;         // sigmoid 0.5-fold (c-gate 32-47 unscaled)
        wbuf[k * 64 + n] = v;
    }
    if (tid < 16)
        epi[tid] = make_float4(0.5f * wp[tid], 0.5f * wp[16 + tid],
                               0.5f * wp[32 + tid], wl[tid]);
    if (tid == 0) sbl = blin[0];
    __syncthreads();

    // ---- B fragments: fp16 hi only (residual dropped; A carries full precision) ----
    u32 Bh[8][2][2];
#pragma unroll
    for (int j = 0; j < 8; ++j) {
        const int n = 8 * j + r0;                 // fragment col = groupID
#pragma unroll
        for (int s = 0; s < 2; ++s)
#pragma unroll
            for (int br = 0; br < 2; ++br) {
                const int kk = s * 16 + br * 8 + 2 * m;
                Bh[j][s][br] = pack2h(wbuf[kk * 64 + n], wbuf[(kk + 1) * 64 + n]);
            }
    }
    const float bl = sbl;
    __syncthreads();                              // wbuf reads done before ring reuse

    const int ngroups = (N + GROUP - 1) / GROUP;
    const int stride  = (int)gridDim.x * WPB;
    const int g0      = (int)blockIdx.x * WPB + warp;
    if (g0 >= ngroups) return;

    const int nmax0 = (N >= GROUP) ? (N - GROUP) : 0;
    u32 sbase   = (u32)__cvta_generic_to_shared(&ring[warp][0][0]);
    u32 epibase = (u32)__cvta_generic_to_shared(&epi[0]);

    // ---- prologue: fill stages 0..2 ----
#pragma unroll
    for (int st = 0; st < 3; ++st) {
        int gg = g0 + st * stride;
        int n0 = (gg < ngroups) ? gg * GROUP : nmax0;
        if (n0 > nmax0) n0 = nmax0;
        issue_group(sbase + st * ST_BYTES, lane, n0, x, h, c);
        cp_commit();
    }

    int st = 0;
    for (int g = g0; g < ngroups; g += stride) {
        cp_wait2();
        __syncwarp();

        // prefetch stage st+3 (distance ~= 2 full compute-groups)
        {
            int gg = g + 3 * stride;
            int n0 = (gg < ngroups) ? gg * GROUP : nmax0;
            if (n0 > nmax0) n0 = nmax0;
            issue_group(sbase + ((st + 3) & 3) * ST_BYTES, lane, n0, x, h, c);
            cp_commit();
        }

        const float* S = &ring[warp][st][0];
        const int nb = g * GROUP;

        // ---- build A fragments (rows r0, r0+8), K=32 with bias col 24 ----
        u32 Ah[2][4], Al[2][4];
        float cv[2][4];
#pragma unroll
        for (int ri = 0; ri < 2; ++ri) {
            const int row = r0 + 8 * ri;
            float2 xp = *(const float2*)(S + ST_X + row * 8 + 2 * m);       // k 0-7
            float2 h1 = *(const float2*)(S + ST_H + row * 16 + 2 * m);      // k 8-15
            float2 h2 = *(const float2*)(S + ST_H + row * 16 + 8 + 2 * m);  // k 16-23
            split2h(xp.x, xp.y, Ah[0][0 + ri], Al[0][0 + ri]);
            split2h(h1.x, h1.y, Ah[0][2 + ri], Al[0][2 + ri]);
            split2h(h2.x, h2.y, Ah[1][0 + ri], Al[1][0 + ri]);
            Ah[1][2 + ri] = (m == 0) ? 0x00003C00u : 0u;   // bias col: f16(1.0) @ k=24
            Al[1][2 + ri] = 0u;
            // hoist c loads: LDS latency overlaps the MMA block below
            float2 ca = *(const float2*)(S + ST_C + row * 16 + 2 * m);
            float2 cb = *(const float2*)(S + ST_C + row * 16 + 8 + 2 * m);
            cv[ri][0] = ca.x; cv[ri][1] = ca.y; cv[ri][2] = cb.x; cv[ri][3] = cb.y;
        }

        // ---- MMA: D = (Ah + Al) * Bh  (2 products, 8 independent n-tiles) ----
        float acc[8][4];
        const float zero4[4] = {0.0f, 0.0f, 0.0f, 0.0f};
#pragma unroll
        for (int j = 0; j < 8; ++j) {
            mma16816(acc[j], Ah[0], Bh[j][0], zero4);
            mma16816(acc[j], Ah[1], Bh[j][1], acc[j]);
            mma16816(acc[j], Al[0], Bh[j][0], acc[j]);
            mma16816(acc[j], Al[1], Bh[j][1], acc[j]);
        }

        // ---- epilogue: 2 rows x 4 features per thread ----
        float4 wq[4];
#pragma unroll
        for (int di = 0; di < 4; ++di) {
            const int dd = (di < 2) ? (2 * m + di) : (8 + 2 * m + (di - 2));
            float4 v;
            asm volatile("ld.shared.v4.f32 {%0,%1,%2,%3}, [%4];"
                         : "=f"(v.x), "=f"(v.y), "=f"(v.z), "=f"(v.w)
                         : "r"(epibase + dd * 16));
            wq[di] = v;
        }

#pragma unroll
        for (int ri = 0; ri < 2; ++ri) {
            const int row = r0 + 8 * ri;
            const int n = nb + row;

            float hn[4], cn[4], racc = 0.0f;
#pragma unroll
            for (int di = 0; di < 4; ++di) {
                const int jb = di >> 1;
                const int ci = ri * 2 + (di & 1);
                const float gi = acc[jb][ci];
                const float gf = acc[jb + 2][ci];
                const float gc = acc[jb + 4][ci];
                const float go = acc[jb + 6][ci];
                const float cvd = cv[ri][di];
                const float4 w = wq[di];
                const float iv = fmaf(0.5f, tanh_a(fmaf(w.x, cvd, gi)), 0.5f);
                const float fv = fmaf(0.5f, tanh_a(fmaf(w.y, cvd, gf)), 0.5f);
                const float tv = tanh_a(gc);
                const float cnv = fmaf(fv, cvd, iv * tv);
                const float ov = fmaf(0.5f, tanh_a(fmaf(w.z, cnv, go)), 0.5f);
                const float hnv = ov * tanh_a(cnv);
                cn[di] = cnv; hn[di] = hnv;
                racc = fmaf(fmaxf(hnv, 0.0f), w.w, racc);
            }
            // quad reduction (threads 4r..4r+3 cover all 16 features)
            racc += __shfl_xor_sync(0xffffffffu, racc, 1);
            racc += __shfl_xor_sync(0xffffffffu, racc, 2);

            if (n < N) {
                float2* cp2 = (float2*)(c_new + (size_t)n * 16 + 2 * m);
                float2* hp2 = (float2*)(h_new + (size_t)n * 16 + 2 * m);
                cp2[0] = make_float2(cn[0], cn[1]);
                cp2[4] = make_float2(cn[2], cn[3]);
                hp2[0] = make_float2(hn[0], hn[1]);
                hp2[4] = make_float2(hn[2], hn[3]);
                if (m == 0) out[n] = racc + bl;
            }
        }

        __syncwarp();
        st = (st + 1) & 3;
    }
    cp_wait0();
}

extern "C" void kernel_launch(void* const* d_in, const int* in_sizes, int n_in,
                              void* d_out, int out_size) {
    // metadata order: x, edge_index(unused), edge_attr(unused), h, c,
    //                 Wx, bx, Wh, bh, w_peep, b_gates, W_lin, b_lin
    const float* x  = (const float*)d_in[0];
    const float* h  = (const float*)d_in[3];
    const float* c  = (const float*)d_in[4];
    const float* Wx = (const float*)d_in[5];
    const float* bx = (const float*)d_in[6];
    const float* Wh = (const float*)d_in[7];
    const float* bh = (const float*)d_in[8];
    const float* wp = (const float*)d_in[9];
    const float* bg = (const float*)d_in[10];
    const float* wl = (const float*)d_in[11];
    const float* bl = (const float*)d_in[12];

    const int N = in_sizes[0] / 8;   // x is (N, 8)

    float* out = (float*)d_out;
    float* hn  = out + (size_t)N;
    float* cn  = hn + (size_t)N * 16;

    const int threads = 128;
    const int blocks  = 592;   // 4 resident blocks x 148 SMs, persistent
    gconvlstm_mma<<<blocks, threads>>>(x, h, c, Wx, bx, Wh, bh, wp, bg, wl, bl,
                                       out, hn, cn, N);
}

// round 17
// speedup vs baseline: 1.0850x; 1.0850x over previous
#include <cuda_runtime.h>
#include <cstdint>

typedef unsigned int u32;

// ---------- MUFU.TANH ----------
__device__ __forceinline__ float tanh_a(float x) {
    float r; asm("tanh.approx.f32 %0, %1;" : "=f"(r) : "f"(x)); return r;
}
// pack bf16x2: lo half = first arg, hi half = second arg
__device__ __forceinline__ u32 bfpair(float lo, float hi) {
    u32 r; asm("cvt.rn.bf16x2.f32 %0, %1, %2;" : "=r"(r) : "f"(hi), "f"(lo)); return r;
}
// fp32 pair -> bf16x2 hi + bf16x2 lo (residual)
__device__ __forceinline__ void split2(float a0, float a1, u32& ph, u32& pl) {
    ph = bfpair(a0, a1);
    float h0 = __uint_as_float(ph << 16);
    float h1 = __uint_as_float(ph & 0xFFFF0000u);
    pl = bfpair(a0 - h0, a1 - h1);
}

// ---------- warp MMA: D(16x8) += A(16x16,bf16,row) * B(16x8,bf16,col) ----------
__device__ __forceinline__ void mma16816(float* d, const u32* a, const u32* b,
                                         const float* c) {
    asm("mma.sync.aligned.m16n8k16.row.col.f32.bf16.bf16.f32 "
        "{%0,%1,%2,%3}, {%4,%5,%6,%7}, {%8,%9}, {%10,%11,%12,%13};"
        : "=f"(d[0]), "=f"(d[1]), "=f"(d[2]), "=f"(d[3])
        : "r"(a[0]), "r"(a[1]), "r"(a[2]), "r"(a[3]),
          "r"(b[0]), "r"(b[1]),
          "f"(c[0]), "f"(c[1]), "f"(c[2]), "f"(c[3]));
}

// ---------- cp.async ----------
__device__ __forceinline__ void cp16(u32 dst, const float* src) {
    asm volatile("cp.async.cg.shared.global [%0], [%1], 16;" :: "r"(dst), "l"(src));
}
__device__ __forceinline__ void cp_commit() { asm volatile("cp.async.commit_group;"); }
__device__ __forceinline__ void cp_wait2()  { asm volatile("cp.async.wait_group 2;"); }
__device__ __forceinline__ void cp_wait0()  { asm volatile("cp.async.wait_group 0;"); }

#define WPB    4
#define STAGES 4
#define GROUP  16
// stage float layout: x[16][8] @0, h[16][16] @128, c[16][16] @384
#define ST_X 0
#define ST_H 128
#define ST_C 384
#define ST_F 640
#define ST_BYTES (ST_F * 4)

__device__ __forceinline__ void issue_group(u32 sb, int lane, int n0,
                                            const float* __restrict__ x,
                                            const float* __restrict__ h,
                                            const float* __restrict__ c)
{
    const int l4 = lane * 4;
    const int l16 = lane * 16;
    cp16(sb + ST_H * 4 + l16,         h + n0 * 16 + l4);
    cp16(sb + (ST_H + 128) * 4 + l16, h + n0 * 16 + 128 + l4);
    cp16(sb + ST_C * 4 + l16,         c + n0 * 16 + l4);
    cp16(sb + (ST_C + 128) * 4 + l16, c + n0 * 16 + 128 + l4);
    cp16(sb + ST_X * 4 + l16,         x + n0 * 8 + l4);
}

__global__ __launch_bounds__(128, 3)
void gconvlstm_mma(const float* __restrict__ x,
                   const float* __restrict__ h,
                   const float* __restrict__ c,
                   const float* __restrict__ Wx, const float* __restrict__ bx,
                   const float* __restrict__ Wh, const float* __restrict__ bh,
                   const float* __restrict__ wp, const float* __restrict__ bg,
                   const float* __restrict__ wl, const float* __restrict__ blin,
                   float* __restrict__ out,
                   float* __restrict__ h_new,
                   float* __restrict__ c_new,
                   int N)
{
    __shared__ __align__(16) float ring[WPB][STAGES][ST_F];   // 40960 B (wbuf overlaid)
    __shared__ __align__(16) float4 epi[16];                  // {0.5wp0,0.5wp1,0.5wp2,wld}
    __shared__ float sbl;

    const int tid  = threadIdx.x;
    const int lane = tid & 31;
    const int warp = tid >> 5;
    const int m    = lane & 3;     // threadID_in_group
    const int r0   = lane >> 2;    // groupID = fragment row

    // ---- stage weight matrix into smem (OVERLAID on ring; init-only lifetime) ----
    float* wbuf = &ring[0][0][0];                 // [32][64], rows 25-31 zero
    for (int i = tid; i < 32 * 64; i += 128) {
        int k = i >> 6, n = i & 63;
        float v = 0.0f;
        if (k < 8)        v = Wx[k * 64 + n];
        else if (k < 24)  v = Wh[(k - 8) * 64 + n];
        else if (k == 24) v = bx[n] + bh[n] + bg[n];
        if (n < 32 || n >= 48) v *= 0.5f;         // sigmoid 0.5-fold (c-gate 32-47 unscaled)
        wbuf[k * 64 + n] = v;
    }
    if (tid < 16)
        epi[tid] = make_float4(0.5f * wp[tid], 0.5f * wp[16 + tid],
                               0.5f * wp[32 + tid], wl[tid]);
    if (tid == 0) sbl = blin[0];
    __syncthreads();

    // ---- persistent B fragments (hi/lo) in registers ----
    u32 Bh[8][2][2], Bl[8][2][2];
#pragma unroll
    for (int j = 0; j < 8; ++j) {
        const int n = 8 * j + r0;                 // fragment col = groupID
#pragma unroll
        for (int s = 0; s < 2; ++s)
#pragma unroll
            for (int br = 0; br < 2; ++br) {
                const int kk = s * 16 + br * 8 + 2 * m;
                split2(wbuf[kk * 64 + n], wbuf[(kk + 1) * 64 + n],
                       Bh[j][s][br], Bl[j][s][br]);
            }
    }
    // per-thread epi quads for d = {2m, 2m+1, 8+2m, 9+2m}
    float4 wq0 = epi[2 * m],     wq1 = epi[2 * m + 1];
    float4 wq2 = epi[8 + 2 * m], wq3 = epi[9 + 2 * m];
    const float bl = sbl;
    __syncthreads();                              // wbuf reads done before ring reuse

    const int ngroups = (N + GROUP - 1) / GROUP;
    const int stride  = (int)gridDim.x * WPB;
    const int g0      = (int)blockIdx.x * WPB + warp;
    if (g0 >= ngroups) return;

    const int nmax0 = (N >= GROUP) ? (N - GROUP) : 0;
    u32 sbase = (u32)__cvta_generic_to_shared(&ring[warp][0][0]);

    // ---- prologue: fill stages 0..2 ----
#pragma unroll
    for (int st = 0; st < 3; ++st) {
        int gg = g0 + st * stride;
        int n0 = (gg < ngroups) ? gg * GROUP : nmax0;
        if (n0 > nmax0) n0 = nmax0;
        issue_group(sbase + st * ST_BYTES, lane, n0, x, h, c);
        cp_commit();
    }

    int st = 0;
    for (int g = g0; g < ngroups; g += stride) {
        cp_wait2();
        __syncwarp();

        // prefetch stage st+3 (distance ~= 2 full compute-groups)
        {
            int gg = g + 3 * stride;
            int n0 = (gg < ngroups) ? gg * GROUP : nmax0;
            if (n0 > nmax0) n0 = nmax0;
            issue_group(sbase + ((st + 3) & 3) * ST_BYTES, lane, n0, x, h, c);
            cp_commit();
        }

        const float* S = &ring[warp][st][0];
        const int nb = g * GROUP;

        // ---- build A fragments (rows r0, r0+8), K=32 with bias col 24 ----
        u32 Ah[2][4], Al[2][4];
        float cv[2][4];
#pragma unroll
        for (int ri = 0; ri < 2; ++ri) {
            const int row = r0 + 8 * ri;
            float2 xp = *(const float2*)(S + ST_X + row * 8 + 2 * m);       // k 0-7
            float2 h1 = *(const float2*)(S + ST_H + row * 16 + 2 * m);      // k 8-15
            float2 h2 = *(const float2*)(S + ST_H + row * 16 + 8 + 2 * m);  // k 16-23
            split2(xp.x, xp.y, Ah[0][0 + ri], Al[0][0 + ri]);
            split2(h1.x, h1.y, Ah[0][2 + ri], Al[0][2 + ri]);
            split2(h2.x, h2.y, Ah[1][0 + ri], Al[1][0 + ri]);
            Ah[1][2 + ri] = (m == 0) ? 0x00003F80u : 0u;   // bias col: bf16(1.0) @ k=24
            Al[1][2 + ri] = 0u;
            // hoist c loads: LDS latency overlaps the MMA block below
            float2 ca = *(const float2*)(S + ST_C + row * 16 + 2 * m);
            float2 cb = *(const float2*)(S + ST_C + row * 16 + 8 + 2 * m);
            cv[ri][0] = ca.x; cv[ri][1] = ca.y; cv[ri][2] = cb.x; cv[ri][3] = cb.y;
        }

        // ---- MMA: D = Ah*Bh + Ah*Bl + Al*Bh  (8 independent n-tiles) ----
        float acc[8][4];
        const float zero4[4] = {0.0f, 0.0f, 0.0f, 0.0f};
#pragma unroll
        for (int j = 0; j < 8; ++j) {
            mma16816(acc[j], Ah[0], Bh[j][0], zero4);
            mma16816(acc[j], Ah[1], Bh[j][1], acc[j]);
            mma16816(acc[j], Ah[0], Bl[j][0], acc[j]);
            mma16816(acc[j], Ah[1], Bl[j][1], acc[j]);
            mma16816(acc[j], Al[0], Bh[j][0], acc[j]);
            mma16816(acc[j], Al[1], Bh[j][1], acc[j]);
        }

        // ---- epilogue: 2 rows x 4 features per thread ----
#pragma unroll
        for (int ri = 0; ri < 2; ++ri) {
            const int row = r0 + 8 * ri;
            const int n = nb + row;

            float hn[4], cn[4], racc = 0.0f;
#pragma unroll
            for (int di = 0; di < 4; ++di) {
                const int jb = di >> 1;
                const int ci = ri * 2 + (di & 1);
                const float gi = acc[jb][ci];
                const float gf = acc[jb + 2][ci];
                const float gc = acc[jb + 4][ci];
                const float go = acc[jb + 6][ci];
                const float cvd = cv[ri][di];
                const float4 w = (di == 0) ? wq0 : (di == 1) ? wq1 : (di == 2) ? wq2 : wq3;
                const float iv = fmaf(0.5f, tanh_a(fmaf(w.x, cvd, gi)), 0.5f);
                const float fv = fmaf(0.5f, tanh_a(fmaf(w.y, cvd, gf)), 0.5f);
                const float tv = tanh_a(gc);
                const float cnv = fmaf(fv, cvd, iv * tv);
                const float ov = fmaf(0.5f, tanh_a(fmaf(w.z, cnv, go)), 0.5f);
                const float hnv = ov * tanh_a(cnv);
                cn[di] = cnv; hn[di] = hnv;
                racc = fmaf(fmaxf(hnv, 0.0f), w.w, racc);
            }
            // quad reduction (threads 4r..4r+3 cover all 16 features)
            racc += __shfl_xor_sync(0xffffffffu, racc, 1);
            racc += __shfl_xor_sync(0xffffffffu, racc, 2);

            if (n < N) {
                float2* cp2 = (float2*)(c_new + (size_t)n * 16 + 2 * m);
                float2* hp2 = (float2*)(h_new + (size_t)n * 16 + 2 * m);
                cp2[0] = make_float2(cn[0], cn[1]);
                cp2[4] = make_float2(cn[2], cn[3]);
                hp2[0] = make_float2(hn[0], hn[1]);
                hp2[4] = make_float2(hn[2], hn[3]);
                if (m == 0) out[n] = racc + bl;
            }
        }

        __syncwarp();
        st = (st + 1) & 3;
    }
    cp_wait0();
}

extern "C" void kernel_launch(void* const* d_in, const int* in_sizes, int n_in,
                              void* d_out, int out_size) {
    // metadata order: x, edge_index(unused), edge_attr(unused), h, c,
    //                 Wx, bx, Wh, bh, w_peep, b_gates, W_lin, b_lin
    const float* x  = (const float*)d_in[0];
    const float* h  = (const float*)d_in[3];
    const float* c  = (const float*)d_in[4];
    const float* Wx = (const float*)d_in[5];
    const float* bx = (const float*)d_in[6];
    const float* Wh = (const float*)d_in[7];
    const float* bh = (const float*)d_in[8];
    const float* wp = (const float*)d_in[9];
    const float* bg = (const float*)d_in[10];
    const float* wl = (const float*)d_in[11];
    const float* bl = (const float*)d_in[12];

    const int N = in_sizes[0] / 8;   // x is (N, 8)

    float* out = (float*)d_out;
    float* hn  = out + (size_t)N;
    float* cn  = hn + (size_t)N * 16;

    const int threads = 128;
    const int blocks  = 444;   // 3 resident blocks x 148 SMs, persistent
    gconvlstm_mma<<<blocks, threads>>>(x, h, c, Wx, bx, Wh, bh, wp, bg, wl, bl,
                                       out, hn, cn, N);
}